// round 1
// baseline (speedup 1.0000x reference)
#include <cuda_runtime.h>
#include <math_constants.h>

// YOLO decode, one warp per detection row.
// Row layout: [conf, tx, ty, tw, th, 80 class logits]  (85 contiguous fp32)
// Output row: [x, y, w, h, class_idx, conf] * (conf > 0.5)

#define WARPS_PER_BLOCK 8
#define THREADS_PER_BLOCK (WARPS_PER_BLOCK * 32)

__global__ __launch_bounds__(THREADS_PER_BLOCK)
void yolo_decode_kernel(const float* __restrict__ p,
                        const float* __restrict__ pre_scale,
                        float* __restrict__ out,   // already offset for this level
                        int S, int dect, int nrows)
{
    __shared__ float smout[WARPS_PER_BLOCK][6];

    const int lane = threadIdx.x & 31;
    const int wib  = threadIdx.x >> 5;                  // warp-in-block
    const int blockRowBase = blockIdx.x * WARPS_PER_BLOCK;
    const int r = blockRowBase + wib;                   // global row within level

    if (r < nrows) {
        const float* row = p + (long long)r * 85;

        // Coalesced row read: lane i -> ch i, i+32, i+64
        const float v0 = row[lane];
        const float v1 = row[32 + lane];
        const float v2 = (lane < 21) ? row[64 + lane] : -CUDART_INF_F;

        // ---- argmax over channels 5..84 (classes 0..79), first-max tie-break ----
        // Candidates per lane in ascending class order:
        //   v0 -> class lane-5  (valid lane>=5)
        //   v1 -> class 27+lane (always valid: ch 32..63)
        //   v2 -> class 59+lane (valid lane<21: ch 64..84)
        float bv = -CUDART_INF_F;
        int   bi = 0x7FFFFFFF;
        if (lane >= 5)            { bv = v0; bi = lane - 5; }
        if (v1 > bv)              { bv = v1; bi = 27 + lane; }
        if (lane < 21 && v2 > bv) { bv = v2; bi = 59 + lane; }

        #pragma unroll
        for (int off = 16; off > 0; off >>= 1) {
            float ov = __shfl_xor_sync(0xFFFFFFFFu, bv, off);
            int   oi = __shfl_xor_sync(0xFFFFFFFFu, bi, off);
            if (ov > bv || (ov == bv && oi < bi)) { bv = ov; bi = oi; }
        }

        // ---- broadcast the 5 box fields from lanes 0..4 of v0 ----
        const float conf = __shfl_sync(0xFFFFFFFFu, v0, 0);
        const float tx   = __shfl_sync(0xFFFFFFFFu, v0, 1);
        const float ty   = __shfl_sync(0xFFFFFFFFu, v0, 2);
        const float tw   = __shfl_sync(0xFFFFFFFFu, v0, 3);
        const float th   = __shfl_sync(0xFFFFFFFFu, v0, 4);

        if (lane == 0) {
            // row r = (i*S + j)*3 + a ; x uses i (dim0), y uses j (dim1)
            const int a = r % 3;
            const int j = (r / 3) % S;
            const int i = r / (3 * S);

            const float inv_grid = 1.0f / (float)S;
            const float inv416   = 1.0f / 416.0f;
            const float aw = pre_scale[(dect * 3 + a) * 2 + 0] * inv416;
            const float ah = pre_scale[(dect * 3 + a) * 2 + 1] * inv416;

            const float sx = 1.0f / (1.0f + expf(-tx));
            const float sy = 1.0f / (1.0f + expf(-ty));

            const float x = (sx + (float)i) * inv_grid;
            const float y = (sy + (float)j) * inv_grid;
            const float w = expf(tw) * aw;
            const float h = expf(th) * ah;

            // reference multiplies the whole row (conf included) by the mask
            const float m = (conf > 0.5f) ? 1.0f : 0.0f;

            smout[wib][0] = x * m;
            smout[wib][1] = y * m;
            smout[wib][2] = w * m;
            smout[wib][3] = h * m;
            smout[wib][4] = (float)bi * m;
            smout[wib][5] = conf * m;
        }
    }

    __syncthreads();

    // Contiguous block store: first 48 threads write up to 8 rows * 6 floats
    const int rowsInBlock = min(WARPS_PER_BLOCK, nrows - blockRowBase);
    if (rowsInBlock > 0) {
        const int t = threadIdx.x;
        const int nf = rowsInBlock * 6;
        if (t < nf) {
            out[(long long)blockRowBase * 6 + t] = smout[t / 6][t % 6];
        }
    }
}

static inline void launch_level(const float* p, const float* pre_scale,
                                float* out, long long rowOffset,
                                int S, int dect)
{
    const int nrows = S * S * 3;
    const int blocks = (nrows + WARPS_PER_BLOCK - 1) / WARPS_PER_BLOCK;
    yolo_decode_kernel<<<blocks, THREADS_PER_BLOCK>>>(
        p, pre_scale, out + rowOffset * 6, S, dect, nrows);
}

extern "C" void kernel_launch(void* const* d_in, const int* in_sizes, int n_in,
                              void* d_out, int out_size)
{
    const float* small     = (const float*)d_in[0];  // 104*104*3*85
    const float* middle    = (const float*)d_in[1];  // 208*208*3*85
    const float* large     = (const float*)d_in[2];  // 416*416*3*85
    const float* pre_scale = (const float*)d_in[3];  // 6*3*2
    float* out = (float*)d_out;

    const long long rows_s = 104LL * 104 * 3;   // 32448
    const long long rows_m = 208LL * 208 * 3;   // 129792

    launch_level(small,  pre_scale, out, 0,               104, 3);
    launch_level(middle, pre_scale, out, rows_s,          208, 4);
    launch_level(large,  pre_scale, out, rows_s + rows_m, 416, 5);
}

// round 2
// speedup vs baseline: 2.5163x; 2.5163x over previous
#include <cuda_runtime.h>
#include <math_constants.h>

// YOLO decode, thread-per-row with coalesced shared staging.
// Row layout: [conf, tx, ty, tw, th, 80 class logits]  (85 contiguous fp32)
// Output row: [x, y, w, h, class_idx, conf] * (conf > 0.5)

#define ROWS_PER_BLOCK 128
#define THREADS_PER_BLOCK 128
#define ROW_F 85

__global__ __launch_bounds__(THREADS_PER_BLOCK)
void yolo_decode_kernel(const float* __restrict__ p,
                        const float* __restrict__ pre_scale,
                        float* __restrict__ out,   // already offset for this level
                        int S, int dect, int nrows)
{
    // 128 rows * 85 floats; stride 85 (gcd(85,32)=1) -> conflict-free column access
    __shared__ float sm[ROWS_PER_BLOCK * ROW_F];

    const int tid = threadIdx.x;
    const int blockRowBase = blockIdx.x * ROWS_PER_BLOCK;

    // ---- Stage: coalesced float4 loads into shared ----
    // blockRowBase*85 is divisible by 4 (128*85 % 4 == 0), and total floats
    // per level (nrows*85) is divisible by 4, so float4 indexing is safe.
    const int rowsHere = min(ROWS_PER_BLOCK, nrows - blockRowBase);
    const int nFloats  = rowsHere * ROW_F;
    const int nF4      = (nFloats + 3) >> 2;   // never exceeds level end
    const float4* __restrict__ g4 = (const float4*)(p + (long long)blockRowBase * ROW_F);
    float4* s4 = (float4*)sm;

    #pragma unroll 8
    for (int i = tid; i < nF4; i += THREADS_PER_BLOCK) {
        s4[i] = g4[i];
    }
    __syncthreads();

    // ---- Process: one thread per row, all reads from shared ----
    const int r = blockRowBase + tid;
    if (r < nrows) {
        const float* rp = &sm[tid * ROW_F];

        const float conf = rp[0];
        const float tx   = rp[1];
        const float ty   = rp[2];
        const float tw   = rp[3];
        const float th   = rp[4];

        // argmax over 80 class logits, first-max tie-break (strict >)
        float bv = rp[5];
        int   bi = 0;
        #pragma unroll 16
        for (int c = 1; c < 80; c++) {
            float v = rp[5 + c];
            if (v > bv) { bv = v; bi = c; }
        }

        // row r = (i*S + j)*3 + a ; x uses i (dim0), y uses j (dim1)
        const int a = r % 3;
        const int q = r / 3;
        const int j = q % S;
        const int i = q / S;

        const float inv_grid = __frcp_rn((float)S);
        const float inv416   = 1.0f / 416.0f;
        const float aw = pre_scale[(dect * 3 + a) * 2 + 0] * inv416;
        const float ah = pre_scale[(dect * 3 + a) * 2 + 1] * inv416;

        const float sx = __fdividef(1.0f, 1.0f + __expf(-tx));
        const float sy = __fdividef(1.0f, 1.0f + __expf(-ty));

        const float x = (sx + (float)i) * inv_grid;
        const float y = (sy + (float)j) * inv_grid;
        const float w = __expf(tw) * aw;
        const float h = __expf(th) * ah;

        // reference multiplies the whole row (conf included) by the mask
        const float m = (conf > 0.5f) ? 1.0f : 0.0f;

        // 24 contiguous bytes per thread; consecutive threads contiguous.
        float2* o2 = (float2*)(out + (long long)r * 6);
        o2[0] = make_float2(x * m, y * m);
        o2[1] = make_float2(w * m, h * m);
        o2[2] = make_float2((float)bi * m, conf * m);
    }
}

static inline void launch_level(const float* p, const float* pre_scale,
                                float* out, long long rowOffset,
                                int S, int dect)
{
    const int nrows = S * S * 3;
    const int blocks = (nrows + ROWS_PER_BLOCK - 1) / ROWS_PER_BLOCK;
    yolo_decode_kernel<<<blocks, THREADS_PER_BLOCK>>>(
        p, pre_scale, out + rowOffset * 6, S, dect, nrows);
}

extern "C" void kernel_launch(void* const* d_in, const int* in_sizes, int n_in,
                              void* d_out, int out_size)
{
    const float* small     = (const float*)d_in[0];  // 104*104*3*85
    const float* middle    = (const float*)d_in[1];  // 208*208*3*85
    const float* large     = (const float*)d_in[2];  // 416*416*3*85
    const float* pre_scale = (const float*)d_in[3];  // 6*3*2
    float* out = (float*)d_out;

    const long long rows_s = 104LL * 104 * 3;   // 32448
    const long long rows_m = 208LL * 208 * 3;   // 129792

    launch_level(small,  pre_scale, out, 0,               104, 3);
    launch_level(middle, pre_scale, out, rows_s,          208, 4);
    launch_level(large,  pre_scale, out, rows_s + rows_m, 416, 5);
}

// round 4
// speedup vs baseline: 4.3702x; 1.7368x over previous
#include <cuda_runtime.h>
#include <cuda_pipeline.h>

// Fused YOLO decode over all three pyramid levels.
// Row layout: [conf, tx, ty, tw, th, 80 class logits] (85 fp32, contiguous)
// Output row: [x, y, w, h, class_idx, conf] * (conf > 0.5)
//
// 10647 tiles of 64 rows. Level boundaries (tile index): [0,507) small,
// [507,2535) middle, [2535,10647) large. 64*85 floats per tile staged via
// cp.async with double buffering; grid-stride persistent blocks.

#define THREADS 128
#define TILE 64
#define ROW_F 85
#define TILE_F (TILE * ROW_F)      // 5440 floats
#define TILE_F4 (TILE_F / 4)       // 1360 float4
#define NT 10647

__device__ __forceinline__
void stage_tile(int t, int tid, float* dst,
                const float* __restrict__ s0,
                const float* __restrict__ s1,
                const float* __restrict__ s2)
{
    const float* src;
    if (t < 507)        src = s0 + (long long)t * TILE_F;
    else if (t < 2535)  src = s1 + (long long)(t - 507) * TILE_F;
    else                src = s2 + (long long)(t - 2535) * TILE_F;
    const float4* g4 = (const float4*)src;
    float4* d4 = (float4*)dst;
    #pragma unroll
    for (int i = 0; i < 10; i++)
        __pipeline_memcpy_async(&d4[tid + i * THREADS], &g4[tid + i * THREADS], 16);
    if (tid < TILE_F4 - 10 * THREADS)   // 1360 - 1280 = 80
        __pipeline_memcpy_async(&d4[1280 + tid], &g4[1280 + tid], 16);
}

__global__ __launch_bounds__(THREADS)
void yolo_decode_fused(const float* __restrict__ s0,
                       const float* __restrict__ s1,
                       const float* __restrict__ s2,
                       const float* __restrict__ ps,
                       float* __restrict__ out)
{
    __shared__ float buf[2][TILE_F];     // 43520 B
    __shared__ float pm[TILE];           // partner max value
    __shared__ int   pi[TILE];           // partner max index (absolute class)
    __shared__ float outbuf[TILE * 6];   // 1536 B

    const int tid = threadIdx.x;
    const int GD  = gridDim.x;

    int t = blockIdx.x;
    if (t < NT) {
        stage_tile(t, tid, buf[0], s0, s1, s2);
        __pipeline_commit();
    }
    int s = 0;

    for (; t < NT; t += GD) {
        const int tn = t + GD;
        const bool pre = (tn < NT);
        if (pre) { stage_tile(tn, tid, buf[s ^ 1], s0, s1, s2); __pipeline_commit(); }

        // per-tile level params (overlaps the cp.async drain)
        int lr, k, dect;
        if (t < 507)        { lr = t * TILE;          k = 0; dect = 3; }
        else if (t < 2535)  { lr = (t - 507) * TILE;  k = 1; dect = 4; }
        else                { lr = (t - 2535) * TILE; k = 2; dect = 5; }
        const int S = 104 << k;

        if (pre) __pipeline_wait_prior(1); else __pipeline_wait_prior(0);
        __syncthreads();

        const float* bc = buf[s];
        const int row  = (tid < TILE) ? tid : (tid - TILE);
        const float* rp = &bc[row * ROW_F];

        // ---- 40-class argmax (strict >, ascending => first-index tie-break) ----
        // group 0 (warps 0-1): classes 0..39 (ch 5..44)
        // group 1 (warps 2-3): classes 40..79 (ch 45..84)
        const float* cp = rp + 5 + ((tid < TILE) ? 0 : 40);
        float m0 = cp[0]; int i0 = 0;
        float m1 = cp[1]; int i1 = 1;
        float m2 = cp[2]; int i2 = 2;
        float m3 = cp[3]; int i3 = 3;
        #pragma unroll
        for (int c = 4; c < 40; c += 4) {
            float v0 = cp[c + 0]; if (v0 > m0) { m0 = v0; i0 = c + 0; }
            float v1 = cp[c + 1]; if (v1 > m1) { m1 = v1; i1 = c + 1; }
            float v2 = cp[c + 2]; if (v2 > m2) { m2 = v2; i2 = c + 2; }
            float v3 = cp[c + 3]; if (v3 > m3) { m3 = v3; i3 = c + 3; }
        }
        // lexicographic merges (value desc, index asc on ties)
        if (m1 > m0 || (m1 == m0 && i1 < i0)) { m0 = m1; i0 = i1; }
        if (m3 > m2 || (m3 == m2 && i3 < i2)) { m2 = m3; i2 = i3; }
        if (m2 > m0 || (m2 == m0 && i2 < i0)) { m0 = m2; i0 = i2; }

        float conf, tx, ty, tw, th;
        if (tid < TILE) {
            conf = rp[0]; tx = rp[1]; ty = rp[2]; tw = rp[3]; th = rp[4];
        } else {
            pm[row] = m0;
            pi[row] = i0 + 40;
        }
        __syncthreads();

        if (tid < TILE) {
            // merge partner half: its indices are all larger, strict > keeps first
            const float om = pm[row];
            int   bi = i0;
            if (om > m0) bi = pi[row];

            const int r = lr + row;          // row within level
            const int a = r % 3;
            const int q = r / 3;
            const int i = (q / 104) >> k;    // floor(q / (104<<k))
            const int j = q - i * S;

            const float inv_grid = __frcp_rn((float)S);
            const float inv416   = 1.0f / 416.0f;
            const float aw = __ldg(&ps[(dect * 3 + a) * 2 + 0]) * inv416;
            const float ah = __ldg(&ps[(dect * 3 + a) * 2 + 1]) * inv416;

            const float sx = __fdividef(1.0f, 1.0f + __expf(-tx));
            const float sy = __fdividef(1.0f, 1.0f + __expf(-ty));

            const float x = (sx + (float)i) * inv_grid;
            const float y = (sy + (float)j) * inv_grid;
            const float w = __expf(tw) * aw;
            const float h = __expf(th) * ah;

            // reference multiplies the whole row (conf included) by the mask
            const float m = (conf > 0.5f) ? 1.0f : 0.0f;

            float* ob = &outbuf[row * 6];
            ob[0] = x * m;
            ob[1] = y * m;
            ob[2] = w * m;
            ob[3] = h * m;
            ob[4] = (float)bi * m;
            ob[5] = conf * m;
        }
        __syncthreads();

        // coalesced tile store: 64 rows * 6 floats = 96 float4
        if (tid < 96) {
            float4* go = (float4*)(out + (long long)t * (TILE * 6));
            go[tid] = ((const float4*)outbuf)[tid];
        }

        s ^= 1;
        // buf[s^1] (the buffer just read) is only overwritten by the stage
        // issued at the top of the next iteration, which all threads reach
        // after the __syncthreads() above — no WAR hazard.
    }
}

extern "C" void kernel_launch(void* const* d_in, const int* in_sizes, int n_in,
                              void* d_out, int out_size)
{
    const float* small     = (const float*)d_in[0];  // 104*104*3*85
    const float* middle    = (const float*)d_in[1];  // 208*208*3*85
    const float* large     = (const float*)d_in[2];  // 416*416*3*85
    const float* pre_scale = (const float*)d_in[3];  // 6*3*2
    float* out = (float*)d_out;

    // 5 blocks/SM * 148 SMs; each block walks ~14 tiles with double buffering
    yolo_decode_fused<<<740, THREADS>>>(small, middle, large, pre_scale, out);
}